// round 2
// baseline (speedup 1.0000x reference)
#include <cuda_runtime.h>
#include <math.h>

#define NB 16
#define NA 65472
#define NC 81
#define NG 50
#define POS_TH 0.5f

__device__ float g_mining[NB * NA];
__device__ float g_best_iou[NB * NA];
__device__ int   g_best_idx[NB * NA];
__device__ unsigned long long g_best_anchor[NB * NG];
__device__ double g_pos_ce;
__device__ double g_loc_sum;
__device__ int    g_pos_cnt[NB];
__device__ unsigned g_thr_u[NB];
__device__ float  g_thr_v[NB];
__device__ int    g_ties[NB];
__device__ double g_neg_sum[NB];

__device__ __forceinline__ unsigned fmap(float v) {
    unsigned u = __float_as_uint(v);
    return (u & 0x80000000u) ? ~u : (u | 0x80000000u);
}
__device__ __forceinline__ float funmap(unsigned u) {
    unsigned b = (u & 0x80000000u) ? (u & 0x7FFFFFFFu) : ~u;
    return __uint_as_float(b);
}

// ---------------------------------------------------------------- K0: init
__global__ void k0_init() {
    int t = threadIdx.x;
    if (t == 0) { g_pos_ce = 0.0; g_loc_sum = 0.0; }
    if (t < NB) { g_pos_cnt[t] = 0; g_neg_sum[t] = 0.0; }
    for (int i = t; i < NB * NG; i += blockDim.x) g_best_anchor[i] = 0ull;
}

// ------------------------------------------------- K1: logsumexp -> mining
// warp per anchor; 81 floats read coalesced as 3 strided lane-loads.
__global__ void k1_lse(const float* __restrict__ conf) {
    int warp = threadIdx.x >> 5;
    int lane = threadIdx.x & 31;
    int a = blockIdx.x * (blockDim.x >> 5) + warp;
    int b = blockIdx.y;
    const float* p = conf + ((size_t)b * NA + a) * NC;
    float x0 = p[lane];
    float x1 = p[32 + lane];
    float s = __expf(x0) + __expf(x1);
    if (lane < NC - 64) s += __expf(p[64 + lane]);
    #pragma unroll
    for (int off = 16; off; off >>= 1) s += __shfl_xor_sync(0xffffffffu, s, off);
    if (lane == 0) g_mining[(size_t)b * NA + a] = __logf(s) - x0;  // lse - conf[...,0]
}

// -------------------------------------------------------- K2: IoU matching
__global__ void k2_match(const float* __restrict__ gts, const int* __restrict__ counts,
                         const float* __restrict__ anchors) {
    __shared__ float4 sbox[NG];
    __shared__ float  sarea[NG];
    int b = blockIdx.y;
    int tid = threadIdx.x;
    int a = blockIdx.x * blockDim.x + tid;
    int lane = tid & 31;
    if (tid < NG) {
        const float* gp = gts + ((size_t)b * NG + tid) * 5;
        float4 bx = make_float4(gp[0], gp[1], gp[2], gp[3]);
        sbox[tid] = bx;
        sarea[tid] = (bx.z - bx.x) * (bx.w - bx.y);
    }
    __syncthreads();
    int count = counts[b];
    float ax0 = 0.f, ay0 = 0.f, ax1 = 0.f, ay1 = 0.f;
    if (a < NA) {
        float4 v = reinterpret_cast<const float4*>(anchors)[a];
        ax0 = v.x; ay0 = v.y; ax1 = v.z; ay1 = v.w;
    }
    float areaA = (ax1 - ax0) * (ay1 - ay0);
    float bi = -1.f;
    int bidx = 0;
    for (int g = 0; g < count; ++g) {
        float4 bx = sbox[g];
        float wx = fminf(ax1, bx.z) - fmaxf(ax0, bx.x);
        float wy = fminf(ay1, bx.w) - fmaxf(ay0, bx.y);
        wx = fmaxf(wx, 0.f); wy = fmaxf(wy, 0.f);
        float inter = wx * wy;
        float iou = __fdividef(inter, areaA + sarea[g] - inter + 1e-10f);
        if (iou > bi) { bi = iou; bidx = g; }   // first-max kept (strict >)
        // warp argmax over anchors for best_anchor[g]; ties -> smallest a
        float m = iou;
        #pragma unroll
        for (int off = 16; off; off >>= 1) m = fmaxf(m, __shfl_xor_sync(0xffffffffu, m, off));
        unsigned ball = __ballot_sync(0xffffffffu, iou == m);
        if (lane == (__ffs(ball) - 1)) {
            unsigned long long pk =
                ((unsigned long long)__float_as_uint(iou) << 32) |
                (unsigned)(0xFFFFFFFFu - (unsigned)a);
            atomicMax(&g_best_anchor[b * NG + g], pk);
        }
    }
    if (a < NA) {
        g_best_iou[(size_t)b * NA + a] = bi;
        g_best_idx[(size_t)b * NA + a] = bidx;
    }
}

// ------------------------------- K3: forced-positive scatter (sequential/b)
__global__ void k3_scatter(const int* __restrict__ counts) {
    int b = threadIdx.x;
    if (b >= NB) return;
    int count = counts[b];
    for (int g = 0; g < count; ++g) {   // ascending g: last write wins
        unsigned long long pk = g_best_anchor[b * NG + g];
        int a = (int)(0xFFFFFFFFu - (unsigned)(pk & 0xFFFFFFFFu));
        g_best_idx[(size_t)b * NA + a] = g;
        g_best_iou[(size_t)b * NA + a] = 2.0f;
    }
}

// --------------------------- K4: positives: CE, SmoothL1, mask mining=-inf
__global__ void k4_pos(const float* __restrict__ conf, const float* __restrict__ pred,
                       const float* __restrict__ gts, const float* __restrict__ anchors) {
    int b = blockIdx.y;
    int a = blockIdx.x * blockDim.x + threadIdx.x;
    float ce = 0.f, loc = 0.f;
    bool pos = false;
    if (a < NA) {
        size_t ia = (size_t)b * NA + a;
        float bi = g_best_iou[ia];
        if (bi >= POS_TH) {
            pos = true;
            int g = g_best_idx[ia];
            const float* gp = gts + ((size_t)b * NG + g) * 5;
            int label = (int)gp[4];
            const float* cp = conf + ia * NC;
            float m = g_mining[ia];
            ce = m + cp[0] - cp[label];          // lse - conf[label]
            g_mining[ia] = -INFINITY;
            float4 av = reinterpret_cast<const float4*>(anchors)[a];
            float acx = (av.x + av.z) * 0.5f, acy = (av.y + av.w) * 0.5f;
            float aw = av.z - av.x, ah = av.w - av.y;
            float mcx = (gp[0] + gp[2]) * 0.5f, mcy = (gp[1] + gp[3]) * 0.5f;
            float mw = gp[2] - gp[0], mh = gp[3] - gp[1];
            float t0 = (mcx - acx) / (aw * 0.1f);
            float t1 = (mcy - acy) / (ah * 0.1f);
            float t2 = logf(mw / aw + 1e-10f) / 0.2f;
            float t3 = logf(mh / ah + 1e-10f) / 0.2f;
            float4 pv = reinterpret_cast<const float4*>(pred)[ia];
            const float BETA = (float)(1.0 / 9.0);
            float d;
            d = fabsf(pv.x - t0); loc += (d < BETA) ? 0.5f * d * d / BETA : d - 0.5f * BETA;
            d = fabsf(pv.y - t1); loc += (d < BETA) ? 0.5f * d * d / BETA : d - 0.5f * BETA;
            d = fabsf(pv.z - t2); loc += (d < BETA) ? 0.5f * d * d / BETA : d - 0.5f * BETA;
            d = fabsf(pv.w - t3); loc += (d < BETA) ? 0.5f * d * d / BETA : d - 0.5f * BETA;
        }
    }
    int cnt = __popc(__ballot_sync(0xffffffffu, pos));
    #pragma unroll
    for (int off = 16; off; off >>= 1) {
        ce  += __shfl_xor_sync(0xffffffffu, ce, off);
        loc += __shfl_xor_sync(0xffffffffu, loc, off);
    }
    if ((threadIdx.x & 31) == 0 && cnt > 0) {
        atomicAdd(&g_pos_ce, (double)ce);
        atomicAdd(&g_loc_sum, (double)loc);
        atomicAdd(&g_pos_cnt[b], cnt);
    }
}

// ------------------------- K5: per-batch radix-select of K-th largest mining
__global__ void k5_select() {
    __shared__ int hist[2048];
    __shared__ unsigned s_pref;
    __shared__ int s_rem, s_selbin, s_above;
    int b = blockIdx.x;
    int tid = threadIdx.x;
    const float* base = g_mining + (size_t)b * NA;
    if (tid == 0) {
        int K = 3 * g_pos_cnt[b];
        if (K > NA) K = NA;
        s_rem = K;
        s_pref = 0u;
    }
    for (int pass = 0; pass < 3; ++pass) {
        for (int i = tid; i < 2048; i += blockDim.x) hist[i] = 0;
        __syncthreads();
        unsigned pref = s_pref;
        int nb = (pass == 2) ? 1024 : 2048;
        for (int i = tid; i < NA; i += blockDim.x) {
            unsigned u = fmap(base[i]);
            unsigned bin; bool ok;
            if (pass == 0)      { ok = true;                 bin = u >> 21; }
            else if (pass == 1) { ok = ((u >> 21) == pref);  bin = (u >> 10) & 0x7FFu; }
            else                { ok = ((u >> 10) == pref);  bin = u & 0x3FFu; }
            if (ok) atomicAdd(&hist[bin], 1);
        }
        __syncthreads();
        if (tid < 32) {
            int lane = tid;
            int cs = nb >> 5;
            int s = 0;
            for (int k = 0; k < cs; k++) s += hist[lane * cs + k];
            int inc = s;
            #pragma unroll
            for (int off = 1; off < 32; off <<= 1) {
                int t = __shfl_down_sync(0xffffffffu, inc, off);
                if (lane + off < 32) inc += t;
            }
            int exc = inc - s;             // count in chunks strictly above
            int remv = s_rem;
            bool hit = (exc < remv) && (inc >= remv);
            unsigned bal = __ballot_sync(0xffffffffu, hit);
            int src = __ffs(bal) - 1;
            if (lane == src) {
                int cum = exc, selbin = lane * cs;
                for (int bb = lane * cs + cs - 1; bb >= lane * cs; --bb) {
                    int h = hist[bb];
                    if (cum + h >= remv) { selbin = bb; break; }
                    cum += h;
                }
                s_selbin = selbin;
                s_above = cum;
            }
        }
        __syncthreads();
        if (tid == 0) {
            s_rem -= s_above;
            s_pref = (pass == 0) ? (unsigned)s_selbin
                                 : ((s_pref << ((pass == 2) ? 10 : 11)) | (unsigned)s_selbin);
        }
        __syncthreads();
    }
    if (tid == 0) {
        unsigned ut = s_pref;
        g_thr_u[b] = ut;
        g_ties[b] = s_rem;
        g_thr_v[b] = funmap(ut);
    }
}

// -------------------------------- K6: per-batch sum of top-K mining values
__global__ void k6_sum() {
    __shared__ double sred[32];
    int b = blockIdx.x, tid = threadIdx.x;
    unsigned ut = g_thr_u[b];
    const float* base = g_mining + (size_t)b * NA;
    double s = 0.0;
    for (int i = tid; i < NA; i += blockDim.x) {
        float v = base[i];
        if (fmap(v) > ut) s += (double)v;
    }
    #pragma unroll
    for (int off = 16; off; off >>= 1) s += __shfl_xor_sync(0xffffffffu, s, off);
    if ((tid & 31) == 0) sred[tid >> 5] = s;
    __syncthreads();
    if (tid < 32) {
        double v = (tid < (int)(blockDim.x >> 5)) ? sred[tid] : 0.0;
        #pragma unroll
        for (int off = 16; off; off >>= 1) v += __shfl_xor_sync(0xffffffffu, v, off);
        if (tid == 0) {
            float tv = g_thr_v[b];
            if (isfinite(tv)) v += (double)g_ties[b] * (double)tv;  // tie values at threshold
            g_neg_sum[b] = v;
        }
    }
}

// ------------------------------------------------------------ K7: finalize
__global__ void k7_final(float* __restrict__ out) {
    if (threadIdx.x == 0) {
        int np = 0; double ns = 0.0;
        for (int b = 0; b < NB; b++) { np += g_pos_cnt[b]; ns += g_neg_sum[b]; }
        float npf = fmaxf(1.f, (float)np);
        double denom = (double)npf * 4.0;
        out[0] = (float)(g_loc_sum / denom);          // localisation_loss
        out[1] = (float)((g_pos_ce + ns) / denom);    // classification_loss
    }
}

extern "C" void kernel_launch(void* const* d_in, const int* in_sizes, int n_in,
                              void* d_out, int out_size) {
    const float* conf    = (const float*)d_in[0];
    const float* pred    = (const float*)d_in[1];
    const float* gts     = (const float*)d_in[2];
    const int*   counts  = (const int*)d_in[3];
    const float* anchors = (const float*)d_in[4];
    float* out = (float*)d_out;

    k0_init<<<1, 256>>>();
    k1_lse<<<dim3(NA / 8, NB), 256>>>(conf);
    k2_match<<<dim3((NA + 255) / 256, NB), 256>>>(gts, counts, anchors);
    k3_scatter<<<1, 32>>>(counts);
    k4_pos<<<dim3((NA + 255) / 256, NB), 256>>>(conf, pred, gts, anchors);
    k5_select<<<NB, 1024>>>();
    k6_sum<<<NB, 1024>>>();
    k7_final<<<1, 32>>>(out);
}

// round 3
// speedup vs baseline: 1.2752x; 1.2752x over previous
#include <cuda_runtime.h>
#include <math.h>

#define NB 16
#define NA 65472
#define NC 81
#define NG 50
#define POS_TH 0.5f

__device__ float g_mining[NB * NA];
__device__ float g_best_iou[NB * NA];
__device__ int   g_best_idx[NB * NA];
__device__ unsigned long long g_best_anchor[NB * NG];
__device__ double g_pos_ce;
__device__ double g_loc_sum;
__device__ int    g_pos_cnt[NB];
__device__ double g_neg_sum[NB];

__device__ __forceinline__ unsigned fmap(float v) {
    unsigned u = __float_as_uint(v);
    return (u & 0x80000000u) ? ~u : (u | 0x80000000u);
}
__device__ __forceinline__ float funmap(unsigned u) {
    unsigned b = (u & 0x80000000u) ? (u & 0x7FFFFFFFu) : ~u;
    return __uint_as_float(b);
}

// ---------------------------------------------------------------- K0: init
__global__ void k0_init() {
    int t = threadIdx.x;
    if (t == 0) { g_pos_ce = 0.0; g_loc_sum = 0.0; }
    if (t < NB) { g_pos_cnt[t] = 0; g_neg_sum[t] = 0.0; }
}

// ------------------------------------------------- K1: logsumexp -> mining
// warp per anchor; 81 floats read as 3 strided lane-loads (coalesced).
__global__ void k1_lse(const float* __restrict__ conf) {
    int warp = threadIdx.x >> 5;
    int lane = threadIdx.x & 31;
    int a = blockIdx.x * (blockDim.x >> 5) + warp;
    int b = blockIdx.y;
    const float* p = conf + ((size_t)b * NA + a) * NC;
    float x0 = p[lane];
    float x1 = p[32 + lane];
    float s = __expf(x0) + __expf(x1);
    if (lane < NC - 64) s += __expf(p[64 + lane]);
    #pragma unroll
    for (int off = 16; off; off >>= 1) s += __shfl_xor_sync(0xffffffffu, s, off);
    if (lane == 0) g_mining[(size_t)b * NA + a] = __logf(s) - x0;  // lse - conf[...,0]
}

// ------------------------------------ K2a: per-anchor best IoU (no atomics)
__global__ void k2a_match(const float* __restrict__ gts, const int* __restrict__ counts,
                          const float* __restrict__ anchors) {
    __shared__ float4 sbox[NG];
    __shared__ float  sarea[NG];
    int b = blockIdx.y;
    int tid = threadIdx.x;
    int a = blockIdx.x * blockDim.x + tid;
    if (tid < NG) {
        const float* gp = gts + ((size_t)b * NG + tid) * 5;
        float4 bx = make_float4(gp[0], gp[1], gp[2], gp[3]);
        sbox[tid] = bx;
        sarea[tid] = (bx.z - bx.x) * (bx.w - bx.y);
    }
    __syncthreads();
    if (a >= NA) return;
    int count = counts[b];
    float4 v = reinterpret_cast<const float4*>(anchors)[a];
    float areaA = (v.z - v.x) * (v.w - v.y);
    float bi = -1.f;
    int bidx = 0;
    for (int g = 0; g < count; ++g) {
        float4 bx = sbox[g];
        float wx = fminf(v.z, bx.z) - fmaxf(v.x, bx.x);
        float wy = fminf(v.w, bx.w) - fmaxf(v.y, bx.y);
        wx = fmaxf(wx, 0.f); wy = fmaxf(wy, 0.f);
        float inter = wx * wy;
        float iou = __fdividef(inter, areaA + sarea[g] - inter + 1e-10f);
        if (iou > bi) { bi = iou; bidx = g; }   // first max kept (strict >)
    }
    g_best_iou[(size_t)b * NA + a] = bi;
    g_best_idx[(size_t)b * NA + a] = bidx;
}

// ---------------- K2b: per-(b,g) argmax over anchors, block-local, no atomics
__global__ void k2b_bestanchor(const float* __restrict__ gts, const int* __restrict__ counts,
                               const float* __restrict__ anchors) {
    __shared__ unsigned long long sred[8];
    int b = blockIdx.y;
    int g = blockIdx.x;
    if (g >= counts[b]) return;
    int tid = threadIdx.x;
    const float* gp = gts + ((size_t)b * NG + g) * 5;
    float bx0 = gp[0], by0 = gp[1], bx1 = gp[2], by1 = gp[3];
    float areaB = (bx1 - bx0) * (by1 - by0);
    unsigned long long best = 0ull;
    for (int a = tid; a < NA; a += blockDim.x) {
        float4 v = reinterpret_cast<const float4*>(anchors)[a];
        float wx = fminf(v.z, bx1) - fmaxf(v.x, bx0);
        float wy = fminf(v.w, by1) - fmaxf(v.y, by0);
        wx = fmaxf(wx, 0.f); wy = fmaxf(wy, 0.f);
        float inter = wx * wy;
        float areaA = (v.z - v.x) * (v.w - v.y);
        float iou = __fdividef(inter, areaA + areaB - inter + 1e-10f);
        unsigned long long pk =
            ((unsigned long long)__float_as_uint(iou) << 32) |
            (unsigned)(0xFFFFFFFFu - (unsigned)a);          // ties -> smallest a
        if (pk > best) best = pk;
    }
    #pragma unroll
    for (int off = 16; off; off >>= 1) {
        unsigned long long o = __shfl_xor_sync(0xffffffffu, best, off);
        if (o > best) best = o;
    }
    if ((tid & 31) == 0) sred[tid >> 5] = best;
    __syncthreads();
    if (tid < 32) {
        unsigned long long v = (tid < (int)(blockDim.x >> 5)) ? sred[tid] : 0ull;
        #pragma unroll
        for (int off = 4; off; off >>= 1) {
            unsigned long long o = __shfl_xor_sync(0xffffffffu, v, off);
            if (o > v) v = o;
        }
        if (tid == 0) g_best_anchor[b * NG + g] = v;
    }
}

// ------------------ K3: parallel forced-positive scatter with last-wins dedup
__global__ void k3_scatter(const int* __restrict__ counts) {
    __shared__ int s_anch[NB * 64];
    __shared__ int s_cnt[NB];
    int tid = threadIdx.x;
    int b = tid >> 6;       // 64 threads per batch (NG=50 < 64)
    int g = tid & 63;
    if (g == 0 && b < NB) s_cnt[b] = counts[b];
    __syncthreads();
    int cnt = (b < NB) ? s_cnt[b] : 0;
    bool act = (b < NB) && (g < cnt);
    int a = -1;
    if (act) {
        unsigned long long pk = g_best_anchor[b * NG + g];
        a = (int)(0xFFFFFFFFu - (unsigned)(pk & 0xFFFFFFFFu));
    }
    s_anch[tid] = a;
    __syncthreads();
    if (act) {
        bool skip = false;
        for (int g2 = g + 1; g2 < cnt; ++g2)       // last write wins
            if (s_anch[(b << 6) + g2] == a) { skip = true; break; }
        if (!skip) {
            g_best_idx[(size_t)b * NA + a] = g;
            g_best_iou[(size_t)b * NA + a] = 2.0f;
        }
    }
}

// --------------------------- K4: positives: CE, SmoothL1, mask mining=-inf
__global__ void k4_pos(const float* __restrict__ conf, const float* __restrict__ pred,
                       const float* __restrict__ gts, const float* __restrict__ anchors) {
    int b = blockIdx.y;
    int a = blockIdx.x * blockDim.x + threadIdx.x;
    float ce = 0.f, loc = 0.f;
    bool pos = false;
    if (a < NA) {
        size_t ia = (size_t)b * NA + a;
        float bi = g_best_iou[ia];
        if (bi >= POS_TH) {
            pos = true;
            int g = g_best_idx[ia];
            const float* gp = gts + ((size_t)b * NG + g) * 5;
            int label = (int)gp[4];
            const float* cp = conf + ia * NC;
            float m = g_mining[ia];
            ce = m + cp[0] - cp[label];          // lse - conf[label]
            g_mining[ia] = -INFINITY;
            float4 av = reinterpret_cast<const float4*>(anchors)[a];
            float acx = (av.x + av.z) * 0.5f, acy = (av.y + av.w) * 0.5f;
            float aw = av.z - av.x, ah = av.w - av.y;
            float mcx = (gp[0] + gp[2]) * 0.5f, mcy = (gp[1] + gp[3]) * 0.5f;
            float mw = gp[2] - gp[0], mh = gp[3] - gp[1];
            float t0 = (mcx - acx) / (aw * 0.1f);
            float t1 = (mcy - acy) / (ah * 0.1f);
            float t2 = logf(mw / aw + 1e-10f) / 0.2f;
            float t3 = logf(mh / ah + 1e-10f) / 0.2f;
            float4 pv = reinterpret_cast<const float4*>(pred)[ia];
            const float BETA = (float)(1.0 / 9.0);
            float d;
            d = fabsf(pv.x - t0); loc += (d < BETA) ? 0.5f * d * d / BETA : d - 0.5f * BETA;
            d = fabsf(pv.y - t1); loc += (d < BETA) ? 0.5f * d * d / BETA : d - 0.5f * BETA;
            d = fabsf(pv.z - t2); loc += (d < BETA) ? 0.5f * d * d / BETA : d - 0.5f * BETA;
            d = fabsf(pv.w - t3); loc += (d < BETA) ? 0.5f * d * d / BETA : d - 0.5f * BETA;
        }
    }
    int cnt = __popc(__ballot_sync(0xffffffffu, pos));
    #pragma unroll
    for (int off = 16; off; off >>= 1) {
        ce  += __shfl_xor_sync(0xffffffffu, ce, off);
        loc += __shfl_xor_sync(0xffffffffu, loc, off);
    }
    if ((threadIdx.x & 31) == 0 && cnt > 0) {
        atomicAdd(&g_pos_ce, (double)ce);
        atomicAdd(&g_loc_sum, (double)loc);
        atomicAdd(&g_pos_cnt[b], cnt);
    }
}

// ---------- K5: per-batch radix-select of K-th largest mining + top-K sum
__global__ void k5_select_sum() {
    __shared__ int hist[2048];
    __shared__ unsigned s_pref;
    __shared__ int s_rem, s_selbin, s_above;
    __shared__ double sred[32];
    int b = blockIdx.x;
    int tid = threadIdx.x;
    const float* base = g_mining + (size_t)b * NA;
    int K = 3 * g_pos_cnt[b];
    if (K > NA) K = NA;
    if (K <= 0) { if (tid == 0) g_neg_sum[b] = 0.0; return; }
    if (tid == 0) { s_rem = K; s_pref = 0u; }
    __syncthreads();
    for (int pass = 0; pass < 3; ++pass) {
        for (int i = tid; i < 2048; i += blockDim.x) hist[i] = 0;
        __syncthreads();
        unsigned pref = s_pref;
        int nb = (pass == 2) ? 1024 : 2048;
        for (int i = tid; i < NA; i += blockDim.x) {
            unsigned u = fmap(base[i]);
            unsigned bin; bool ok;
            if (pass == 0)      { ok = true;                 bin = u >> 21; }
            else if (pass == 1) { ok = ((u >> 21) == pref);  bin = (u >> 10) & 0x7FFu; }
            else                { ok = ((u >> 10) == pref);  bin = u & 0x3FFu; }
            if (ok) atomicAdd(&hist[bin], 1);
        }
        __syncthreads();
        if (tid < 32) {
            int lane = tid;
            int cs = nb >> 5;
            int s = 0;
            for (int k = 0; k < cs; k++) s += hist[lane * cs + k];
            int inc = s;
            #pragma unroll
            for (int off = 1; off < 32; off <<= 1) {
                int t = __shfl_down_sync(0xffffffffu, inc, off);
                if (lane + off < 32) inc += t;
            }
            int exc = inc - s;             // count in chunks strictly above
            int remv = s_rem;
            bool hit = (exc < remv) && (inc >= remv);
            unsigned bal = __ballot_sync(0xffffffffu, hit);
            int src = __ffs(bal) - 1;
            if (lane == src) {
                int cum = exc, selbin = lane * cs;
                for (int bb = lane * cs + cs - 1; bb >= lane * cs; --bb) {
                    int h = hist[bb];
                    if (cum + h >= remv) { selbin = bb; break; }
                    cum += h;
                }
                s_selbin = selbin;
                s_above = cum;
            }
        }
        __syncthreads();
        if (tid == 0) {
            s_rem -= s_above;
            s_pref = (pass == 0) ? (unsigned)s_selbin
                                 : ((s_pref << ((pass == 2) ? 10 : 11)) | (unsigned)s_selbin);
        }
        __syncthreads();
    }
    // 4th pass: sum all values strictly above the threshold, plus tie term
    unsigned ut = s_pref;
    double s = 0.0;
    for (int i = tid; i < NA; i += blockDim.x) {
        float v = base[i];
        if (fmap(v) > ut) s += (double)v;
    }
    #pragma unroll
    for (int off = 16; off; off >>= 1) s += __shfl_xor_sync(0xffffffffu, s, off);
    if ((tid & 31) == 0) sred[tid >> 5] = s;
    __syncthreads();
    if (tid < 32) {
        double v = (tid < (int)(blockDim.x >> 5)) ? sred[tid] : 0.0;
        #pragma unroll
        for (int off = 16; off; off >>= 1) v += __shfl_xor_sync(0xffffffffu, v, off);
        if (tid == 0) {
            float tv = funmap(ut);
            if (isfinite(tv)) v += (double)s_rem * (double)tv;  // ties at threshold
            g_neg_sum[b] = v;
        }
    }
}

// ------------------------------------------------------------ K7: finalize
__global__ void k7_final(float* __restrict__ out) {
    if (threadIdx.x == 0) {
        int np = 0; double ns = 0.0;
        for (int b = 0; b < NB; b++) { np += g_pos_cnt[b]; ns += g_neg_sum[b]; }
        float npf = fmaxf(1.f, (float)np);
        double denom = (double)npf * 4.0;
        out[0] = (float)(g_loc_sum / denom);          // localisation_loss
        out[1] = (float)((g_pos_ce + ns) / denom);    // classification_loss
    }
}

extern "C" void kernel_launch(void* const* d_in, const int* in_sizes, int n_in,
                              void* d_out, int out_size) {
    const float* conf    = (const float*)d_in[0];
    const float* pred    = (const float*)d_in[1];
    const float* gts     = (const float*)d_in[2];
    const int*   counts  = (const int*)d_in[3];
    const float* anchors = (const float*)d_in[4];
    float* out = (float*)d_out;

    k0_init<<<1, 256>>>();
    k1_lse<<<dim3(NA / 8, NB), 256>>>(conf);
    k2a_match<<<dim3((NA + 255) / 256, NB), 256>>>(gts, counts, anchors);
    k2b_bestanchor<<<dim3(NG, NB), 256>>>(gts, counts, anchors);
    k3_scatter<<<1, 1024>>>(counts);
    k4_pos<<<dim3((NA + 255) / 256, NB), 256>>>(conf, pred, gts, anchors);
    k5_select_sum<<<NB, 1024>>>();
    k7_final<<<1, 32>>>(out);
}